// round 7
// baseline (speedup 1.0000x reference)
#include <cuda_runtime.h>
#include <cuda_bf16.h>
#include <cstdint>

#define N 8192
#define D 128
#define MARGIN 0.3f
#define NCLS 256
#define FINF __int_as_float(0x7f800000)

__device__ __nv_bfloat16 g_x0[N * D];   // hi bf16 split
__device__ __nv_bfloat16 g_x1[N * D];   // lo bf16 split
__device__ float2        g_sqtg[N];     // (sq_norm, target-as-bits)
__device__ int           g_cc[NCLS];
__device__ int           g_is64;
__device__ float4        g_part[4 * N]; // per (half, wc) partial stats
__device__ float         g_bsum[32];

// ---------------- PTX helpers ----------------
__device__ __forceinline__ uint32_t smem_u32(const void* p) {
    uint32_t a;
    asm("{ .reg .u64 t; cvta.to.shared.u64 t, %1; cvt.u32.u64 %0, t; }"
        : "=r"(a) : "l"(p));
    return a;
}
#define CP16(dst, src) \
    asm volatile("cp.async.cg.shared.global [%0], [%1], 16;" \
        :: "r"(dst), "l"(src) : "memory")
#define CP_COMMIT() asm volatile("cp.async.commit_group;" ::: "memory")
#define CP_WAIT(n)  asm volatile("cp.async.wait_group %0;" :: "n"(n) : "memory")

#define LDSM4(r, a) \
    asm volatile("ldmatrix.sync.aligned.m8n8.x4.shared.b16 {%0,%1,%2,%3}, [%4];" \
        : "=r"((r)[0]), "=r"((r)[1]), "=r"((r)[2]), "=r"((r)[3]) : "r"(a))

#define MMA(c, a, b0_, b1_) \
    asm volatile("mma.sync.aligned.m16n8k16.row.col.f32.bf16.bf16.f32 " \
        "{%0,%1,%2,%3},{%4,%5,%6,%7},{%8,%9},{%0,%1,%2,%3};" \
        : "+f"((c)[0]), "+f"((c)[1]), "+f"((c)[2]), "+f"((c)[3]) \
        : "r"((a)[0]), "r"((a)[1]), "r"((a)[2]), "r"((a)[3]), "r"(b0_), "r"(b1_))

// SMEM layout (64KB A, 2x64KB B)
#define OFF_A     0
#define OFF_B0    65536
#define OFF_B1    131072
#define SMEM_REQ  196608

// ---------------------------------------------------------------------------
__global__ void detect_kernel(const unsigned int* __restrict__ t) {
    __shared__ unsigned int sred[256];
    unsigned int acc = 0;
    for (int i = threadIdx.x; i < N / 2; i += 256) acc |= t[2 * i + 1];
    sred[threadIdx.x] = acc;
    __syncthreads();
    for (int s = 128; s > 0; s >>= 1) {
        if (threadIdx.x < s) sred[threadIdx.x] |= sred[threadIdx.x + s];
        __syncthreads();
    }
    if (threadIdx.x == 0) g_is64 = (sred[0] == 0u) ? 1 : 0;
    if (threadIdx.x < NCLS) g_cc[threadIdx.x] = 0;
}

// bf16 split + norms + targets + class histogram.
__global__ void prep_kernel(const float* __restrict__ x, const void* __restrict__ tgt) {
    int lane = threadIdx.x & 31;
    int gw   = (blockIdx.x * 8) + (threadIdx.x >> 5);  // 0..1023
    const float4* X4 = (const float4*)x;
    uint2* O0 = (uint2*)g_x0;
    uint2* O1 = (uint2*)g_x1;
    int is64 = g_is64;

    #pragma unroll
    for (int r = 0; r < 8; r++) {
        int row = gw * 8 + r;
        float4 v = X4[row * 32 + lane];

        __nv_bfloat16 h0 = __float2bfloat16(v.x);
        __nv_bfloat16 h1 = __float2bfloat16(v.y);
        __nv_bfloat16 h2 = __float2bfloat16(v.z);
        __nv_bfloat16 h3 = __float2bfloat16(v.w);
        __nv_bfloat162 p01 = __halves2bfloat162(h0, h1);
        __nv_bfloat162 p23 = __halves2bfloat162(h2, h3);
        O0[row * 32 + lane] = make_uint2(*(uint32_t*)&p01, *(uint32_t*)&p23);

        __nv_bfloat162 q01 = __halves2bfloat162(
            __float2bfloat16(v.x - __bfloat162float(h0)),
            __float2bfloat16(v.y - __bfloat162float(h1)));
        __nv_bfloat162 q23 = __halves2bfloat162(
            __float2bfloat16(v.z - __bfloat162float(h2)),
            __float2bfloat16(v.w - __bfloat162float(h3)));
        O1[row * 32 + lane] = make_uint2(*(uint32_t*)&q01, *(uint32_t*)&q23);

        float s = v.x * v.x + v.y * v.y + v.z * v.z + v.w * v.w;
        #pragma unroll
        for (int o = 16; o > 0; o >>= 1) s += __shfl_xor_sync(0xffffffffu, s, o);
        if (lane == 0) {
            int tg;
            if (is64) tg = (int)((const long long*)tgt)[row];
            else      tg = ((const int*)tgt)[row];
            g_sqtg[row] = make_float2(s, __int_as_float(tg));
            atomicAdd(&g_cc[tg], 1);
        }
    }
}

// ---------------------------------------------------------------------------
// Main: mma.sync bf16-split distance GEMM + fused per-row stats.
// Single barrier per chunk: CP_WAIT(0) -> barrier -> prefetch(c+1) -> compute(c).
// Epilogue sq/tg staged in registers via LDG.128 (no smem stage).
// ---------------------------------------------------------------------------
__global__ void __launch_bounds__(256, 1) main_kernel() {
    extern __shared__ __align__(1024) char smraw[];
    uint32_t sb = smem_u32(smraw);

    int tid  = threadIdx.x;
    int lane = tid & 31;
    int wid  = tid >> 5;
    int wr   = wid >> 1;          // row group (32 rows)
    int wc   = wid & 1;           // col group (64 cols)
    int i0   = (blockIdx.x >> 1) * 128;
    int half = blockIdx.x & 1;
    int jb   = half * 4096;

    // ---- A tile via cp.async (rows i0..i0+127, both splits) ----
    #pragma unroll
    for (int t = 0; t < 16; t++) {
        int idx = tid + t * 256;           // 0..4095 16B chunks
        int s   = idx >> 11;
        int rem = idx & 2047;
        int r   = rem >> 4;
        int kc  = rem & 15;
        const __nv_bfloat16* src = (s ? g_x1 : g_x0) + (i0 + r) * D + kc * 8;
        uint32_t dst = sb + OFF_A + s * 32768 + (kc >> 3) * 16384 + r * 128
                     + (((kc & 7) << 4) ^ ((r & 7) << 4));
        CP16(dst, src);
    }
    CP_COMMIT();

    // ---- B chunk 0 ----
    {
        int j0 = jb;
        #pragma unroll
        for (int t = 0; t < 16; t++) {
            int idx = tid + t * 256;
            int s   = idx >> 11;
            int rem = idx & 2047;
            int r   = rem >> 4;
            int kc  = rem & 15;
            const __nv_bfloat16* src = (s ? g_x1 : g_x0) + (j0 + r) * D + kc * 8;
            uint32_t dst = sb + OFF_B0 + s * 32768 + (kc >> 3) * 16384 + r * 128
                         + (((kc & 7) << 4) ^ ((r & 7) << 4));
            CP16(dst, src);
        }
        CP_COMMIT();
    }

    // ---- per-thread stats for 4 fixed rows ----
    float ps[4], pmax[4], ns[4], nmin[4], sqi[4];
    int tgi[4], rowg[4];
    #pragma unroll
    for (int q = 0; q < 4; q++) {
        rowg[q] = i0 + wr * 32 + q * 8 + (lane >> 2);
        float2 st = g_sqtg[rowg[q]];
        sqi[q] = st.x;
        tgi[q] = __float_as_int(st.y);
        ps[q] = 0.0f; ns[q] = 0.0f; pmax[q] = -FINF; nmin[q] = FINF;
    }
    int colbase = wc * 64 + (lane & 3) * 2;  // epilogue column base

    for (int c = 0; c < 32; c++) {
        int buf = c & 1;
        int j0  = jb + c * 128;

        CP_WAIT(0);        // this thread's chunk-c parts arrived
        __syncthreads();   // publish all parts; compute(c-1) done before prefetch below

        // prefetch chunk c+1 into the other buffer (overlaps compute c)
        if (c + 1 < 32) {
            int jn = jb + (c + 1) * 128;
            uint32_t bdst = sb + ((c + 1) & 1 ? OFF_B1 : OFF_B0);
            #pragma unroll
            for (int t = 0; t < 16; t++) {
                int idx = tid + t * 256;
                int s   = idx >> 11;
                int rem = idx & 2047;
                int r   = rem >> 4;
                int kc  = rem & 15;
                const __nv_bfloat16* src = (s ? g_x1 : g_x0) + (jn + r) * D + kc * 8;
                uint32_t dst = bdst + s * 32768 + (kc >> 3) * 16384 + r * 128
                             + (((kc & 7) << 4) ^ ((r & 7) << 4));
                CP16(dst, src);
            }
            CP_COMMIT();
        }

        // stage epilogue metadata in registers (latency hides under MMAs)
        float4 stv[8];
        #pragma unroll
        for (int ni = 0; ni < 8; ni++)
            stv[ni] = *(const float4*)&g_sqtg[j0 + colbase + ni * 8];

        // ---- compute 128x128 (this warp: 32x64) with 3 bf16-split terms ----
        float acc[2][8][4];
        #pragma unroll
        for (int mi = 0; mi < 2; mi++)
            #pragma unroll
            for (int ni = 0; ni < 8; ni++)
                #pragma unroll
                for (int v = 0; v < 4; v++) acc[mi][ni][v] = 0.0f;

        uint32_t bbuf = sb + (buf ? OFF_B1 : OFF_B0);
        #pragma unroll
        for (int t = 0; t < 3; t++) {
            uint32_t abase = sb + OFF_A + (t == 2 ? 32768 : 0);
            uint32_t bbase = bbuf + (t == 1 ? 32768 : 0);
            #pragma unroll
            for (int kk = 0; kk < 8; kk++) {
                uint32_t af[2][4];
                int kbA = kk * 32 + ((lane >> 4) << 4);
                int hA = kbA >> 7, wA = kbA & 127;
                #pragma unroll
                for (int mi = 0; mi < 2; mi++) {
                    int row = wr * 32 + mi * 16 + (lane & 15);
                    uint32_t ad = abase + hA * 16384 + row * 128
                                + (wA ^ ((row & 7) << 4));
                    LDSM4(af[mi], ad);
                }
                uint32_t bf[4][4];
                int kbB = kk * 32 + (((lane >> 3) & 1) << 4);
                int hB = kbB >> 7, wB = kbB & 127;
                #pragma unroll
                for (int g = 0; g < 4; g++) {
                    int col = wc * 64 + g * 16 + (lane & 7) + (((lane >> 4) & 1) << 3);
                    uint32_t bd = bbase + hB * 16384 + col * 128
                                + (wB ^ ((col & 7) << 4));
                    LDSM4(bf[g], bd);
                }
                #pragma unroll
                for (int mi = 0; mi < 2; mi++)
                    #pragma unroll
                    for (int g = 0; g < 4; g++) {
                        MMA(acc[mi][2 * g],     af[mi], bf[g][0], bf[g][1]);
                        MMA(acc[mi][2 * g + 1], af[mi], bf[g][2], bf[g][3]);
                    }
            }
        }

        // ---- epilogue: fold 32x64 distances into per-row stats ----
        #pragma unroll
        for (int ni = 0; ni < 8; ni++) {
            float4 sv = stv[ni];
            #pragma unroll
            for (int mi = 0; mi < 2; mi++)
                #pragma unroll
                for (int v = 0; v < 4; v++) {
                    int slot = mi * 2 + (v >> 1);
                    int b    = v & 1;
                    float sqj = b ? sv.z : sv.x;
                    int   tgj = __float_as_int(b ? sv.w : sv.y);
                    int cl = colbase + ni * 8 + b;
                    float d2 = fmaxf(fmaf(-2.0f, acc[mi][ni][v], sqi[slot] + sqj),
                                     1e-12f);
                    if (tgj == tgi[slot]) {
                        if (j0 + cl != rowg[slot]) {
                            ps[slot] += d2;
                            pmax[slot] = fmaxf(pmax[slot], d2);
                        }
                    } else {
                        ns[slot] += d2;
                        nmin[slot] = fminf(nmin[slot], d2);
                    }
                }
        }
        // no trailing barrier: next iteration's barrier covers buffer reuse
    }

    // ---- reduce across the 4 lanes sharing each row, write partials ----
    #pragma unroll
    for (int q = 0; q < 4; q++) {
        float a = ps[q], b = pmax[q], cn = ns[q], d = nmin[q];
        #pragma unroll
        for (int o = 1; o <= 2; o <<= 1) {
            a  += __shfl_xor_sync(0xffffffffu, a, o);
            b   = fmaxf(b, __shfl_xor_sync(0xffffffffu, b, o));
            cn += __shfl_xor_sync(0xffffffffu, cn, o);
            d   = fminf(d, __shfl_xor_sync(0xffffffffu, d, o));
        }
        if ((lane & 3) == 0)
            g_part[(half * 2 + wc) * N + rowg[q]] = make_float4(a, b, cn, d);
    }
}

// ---------------------------------------------------------------------------
// Hinge per row (parallel), block partial sums.
// ---------------------------------------------------------------------------
__global__ void hinge_kernel() {
    __shared__ float smr[256];
    int row = blockIdx.x * 256 + threadIdx.x;
    float4 p0 = g_part[row];
    float4 p1 = g_part[N + row];
    float4 p2 = g_part[2 * N + row];
    float4 p3 = g_part[3 * N + row];
    float psum = p0.x + p1.x + p2.x + p3.x;
    float pmax = fmaxf(fmaxf(p0.y, p1.y), fmaxf(p2.y, p3.y));
    float nsum = p0.z + p1.z + p2.z + p3.z;
    float nmin = fminf(fminf(p0.w, p1.w), fminf(p2.w, p3.w));
    int tg = __float_as_int(g_sqtg[row].y);
    int cc = g_cc[tg];
    float sp = psum / (float)(cc - 1);
    float ap = pmax / sp + 0.5f * logf(sp);
    float sn = nsum / (float)(N - cc);
    float an = nmin / sn + 0.5f * logf(sn);
    float h = fmaxf(ap - an + MARGIN, 0.0f);

    smr[threadIdx.x] = h;
    __syncthreads();
    for (int o = 128; o > 0; o >>= 1) {
        if (threadIdx.x < o) smr[threadIdx.x] += smr[threadIdx.x + o];
        __syncthreads();
    }
    if (threadIdx.x == 0) g_bsum[blockIdx.x] = smr[0];
}

__global__ void sum_kernel(float* __restrict__ out) {
    float v = g_bsum[threadIdx.x];
    #pragma unroll
    for (int o = 16; o > 0; o >>= 1) v += __shfl_xor_sync(0xffffffffu, v, o);
    if (threadIdx.x == 0) out[0] = v / (float)N;
}

extern "C" void kernel_launch(void* const* d_in, const int* in_sizes, int n_in,
                              void* d_out, int out_size) {
    (void)in_sizes; (void)n_in; (void)out_size;
    const float* x   = (const float*)d_in[0];
    const void*  tgt = d_in[1];

    detect_kernel<<<1, 256>>>((const unsigned int*)tgt);
    prep_kernel<<<128, 256>>>(x, tgt);

    cudaFuncSetAttribute(main_kernel, cudaFuncAttributeMaxDynamicSharedMemorySize, SMEM_REQ);
    main_kernel<<<128, 256, SMEM_REQ>>>();

    hinge_kernel<<<32, 256>>>();
    sum_kernel<<<1, 32>>>((float*)d_out);
}

// round 10
// speedup vs baseline: 2.0995x; 2.0995x over previous
#include <cuda_runtime.h>
#include <cuda_fp16.h>
#include <cstdint>

#define N 8192
#define D 128
#define MARGIN 0.3f
#define NCLS 256
#define FINF __int_as_float(0x7f800000)

__device__ __half  g_xh[N * D];         // fp16 inputs
__device__ float2  g_sqtg[N];           // (sq_norm fp32, target-as-bits)
__device__ int     g_cc[NCLS];
__device__ int     g_is64;
__device__ float4  g_part[4 * N];       // per (half, wc) partial stats
__device__ float   g_bsum[32];

// ---------------- PTX helpers ----------------
__device__ __forceinline__ uint32_t smem_u32(const void* p) {
    uint32_t a;
    asm("{ .reg .u64 t; cvta.to.shared.u64 t, %1; cvt.u32.u64 %0, t; }"
        : "=r"(a) : "l"(p));
    return a;
}
#define CP16(dst, src) \
    asm volatile("cp.async.cg.shared.global [%0], [%1], 16;" \
        :: "r"(dst), "l"(src) : "memory")
#define CP_COMMIT() asm volatile("cp.async.commit_group;" ::: "memory")
#define CP_WAIT(n)  asm volatile("cp.async.wait_group %0;" :: "n"(n) : "memory")

#define LDSM4(r, a) \
    asm volatile("ldmatrix.sync.aligned.m8n8.x4.shared.b16 {%0,%1,%2,%3}, [%4];" \
        : "=r"((r)[0]), "=r"((r)[1]), "=r"((r)[2]), "=r"((r)[3]) : "r"(a))

#define MMA(c, a, b0_, b1_) \
    asm volatile("mma.sync.aligned.m16n8k16.row.col.f32.f16.f16.f32 " \
        "{%0,%1,%2,%3},{%4,%5,%6,%7},{%8,%9},{%0,%1,%2,%3};" \
        : "+f"((c)[0]), "+f"((c)[1]), "+f"((c)[2]), "+f"((c)[3]) \
        : "r"((a)[0]), "r"((a)[1]), "r"((a)[2]), "r"((a)[3]), "r"(b0_), "r"(b1_))

// SMEM layout (32KB A, 2x32KB B, 1KB stage)
#define OFF_A     0
#define OFF_B0    32768
#define OFF_B1    65536
#define OFF_STAGE 98304
#define SMEM_REQ  (98304 + 1024)

// ---------------------------------------------------------------------------
__global__ void detect_kernel(const unsigned int* __restrict__ t) {
    __shared__ unsigned int sred[256];
    unsigned int acc = 0;
    for (int i = threadIdx.x; i < N / 2; i += 256) acc |= t[2 * i + 1];
    sred[threadIdx.x] = acc;
    __syncthreads();
    for (int s = 128; s > 0; s >>= 1) {
        if (threadIdx.x < s) sred[threadIdx.x] |= sred[threadIdx.x + s];
        __syncthreads();
    }
    if (threadIdx.x == 0) g_is64 = (sred[0] == 0u) ? 1 : 0;
    if (threadIdx.x < NCLS) g_cc[threadIdx.x] = 0;
}

// fp16 convert + fp32 norms + targets + class histogram.
__global__ void prep_kernel(const float* __restrict__ x, const void* __restrict__ tgt) {
    int lane = threadIdx.x & 31;
    int gw   = (blockIdx.x * 8) + (threadIdx.x >> 5);  // 0..1023
    const float4* X4 = (const float4*)x;
    uint2* OH = (uint2*)g_xh;
    int is64 = g_is64;

    #pragma unroll
    for (int r = 0; r < 8; r++) {
        int row = gw * 8 + r;
        float4 v = X4[row * 32 + lane];

        __half2 p01 = __floats2half2_rn(v.x, v.y);
        __half2 p23 = __floats2half2_rn(v.z, v.w);
        OH[row * 32 + lane] = make_uint2(*(uint32_t*)&p01, *(uint32_t*)&p23);

        float s = v.x * v.x + v.y * v.y + v.z * v.z + v.w * v.w;
        #pragma unroll
        for (int o = 16; o > 0; o >>= 1) s += __shfl_xor_sync(0xffffffffu, s, o);
        if (lane == 0) {
            int tg;
            if (is64) tg = (int)((const long long*)tgt)[row];
            else      tg = ((const int*)tgt)[row];
            g_sqtg[row] = make_float2(s, __int_as_float(tg));
            atomicAdd(&g_cc[tg], 1);
        }
    }
}

// ---------------------------------------------------------------------------
// Main: fp16 mma.sync distance GEMM + fused per-row stats.
// R6 pipeline structure (measured best): prefetch -> CP_WAIT(1) -> stage ->
// barrier -> compute -> epilogue -> barrier. Single fp16 term (norms fp32).
// ---------------------------------------------------------------------------
__global__ void __launch_bounds__(256, 1) main_kernel() {
    extern __shared__ __align__(1024) char smraw[];
    uint32_t sb = smem_u32(smraw);
    float2* stage = (float2*)(smraw + OFF_STAGE);

    int tid  = threadIdx.x;
    int lane = tid & 31;
    int wid  = tid >> 5;
    int wr   = wid >> 1;          // row group (32 rows)
    int wc   = wid & 1;           // col group (64 cols)
    int i0   = (blockIdx.x >> 1) * 128;
    int half = blockIdx.x & 1;
    int jb   = half * 4096;

    // ---- A tile via cp.async (128 rows x 128 k fp16 = 32KB) ----
    #pragma unroll
    for (int t = 0; t < 8; t++) {
        int idx = tid + t * 256;           // 0..2047 16B chunks
        int r   = idx >> 4;
        int kc  = idx & 15;
        const __half* src = g_xh + (i0 + r) * D + kc * 8;
        uint32_t dst = sb + OFF_A + (kc >> 3) * 16384 + r * 128
                     + (((kc & 7) << 4) ^ ((r & 7) << 4));
        CP16(dst, src);
    }
    CP_COMMIT();

    // ---- B chunk 0 ----
    #pragma unroll
    for (int t = 0; t < 8; t++) {
        int idx = tid + t * 256;
        int r   = idx >> 4;
        int kc  = idx & 15;
        const __half* src = g_xh + (jb + r) * D + kc * 8;
        uint32_t dst = sb + OFF_B0 + (kc >> 3) * 16384 + r * 128
                     + (((kc & 7) << 4) ^ ((r & 7) << 4));
        CP16(dst, src);
    }
    CP_COMMIT();

    // ---- per-thread stats for 4 fixed rows ----
    float ps[4], pmax[4], ns[4], nmin[4], sqi[4];
    int tgi[4], rowg[4];
    #pragma unroll
    for (int q = 0; q < 4; q++) {
        rowg[q] = i0 + wr * 32 + q * 8 + (lane >> 2);
        float2 st = g_sqtg[rowg[q]];
        sqi[q] = st.x;
        tgi[q] = __float_as_int(st.y);
        ps[q] = 0.0f; ns[q] = 0.0f; pmax[q] = -FINF; nmin[q] = FINF;
    }

    CP_WAIT(0);
    __syncthreads();

    for (int c = 0; c < 32; c++) {
        int buf = c & 1;
        int j0  = jb + c * 128;

        // prefetch next chunk into other buffer
        if (c + 1 < 32) {
            int jn = jb + (c + 1) * 128;
            uint32_t bdst = sb + ((c + 1) & 1 ? OFF_B1 : OFF_B0);
            #pragma unroll
            for (int t = 0; t < 8; t++) {
                int idx = tid + t * 256;
                int r   = idx >> 4;
                int kc  = idx & 15;
                const __half* src = g_xh + (jn + r) * D + kc * 8;
                uint32_t dst = bdst + (kc >> 3) * 16384 + r * 128
                             + (((kc & 7) << 4) ^ ((r & 7) << 4));
                CP16(dst, src);
            }
            CP_COMMIT();
            CP_WAIT(1);
        } else {
            CP_WAIT(0);
        }
        if (tid < 128) stage[tid] = g_sqtg[j0 + tid];
        __syncthreads();  // chunk c data + stage visible

        // ---- compute 128x128 (this warp: 32x64), single fp16 term ----
        float acc[2][8][4];
        #pragma unroll
        for (int mi = 0; mi < 2; mi++)
            #pragma unroll
            for (int ni = 0; ni < 8; ni++)
                #pragma unroll
                for (int v = 0; v < 4; v++) acc[mi][ni][v] = 0.0f;

        uint32_t bbase = sb + (buf ? OFF_B1 : OFF_B0);
        uint32_t abase = sb + OFF_A;
        #pragma unroll
        for (int kk = 0; kk < 8; kk++) {
            uint32_t af[2][4];
            int kbA = kk * 32 + ((lane >> 4) << 4);
            int hA = kbA >> 7, wA = kbA & 127;
            #pragma unroll
            for (int mi = 0; mi < 2; mi++) {
                int row = wr * 32 + mi * 16 + (lane & 15);
                uint32_t ad = abase + hA * 16384 + row * 128
                            + (wA ^ ((row & 7) << 4));
                LDSM4(af[mi], ad);
            }
            uint32_t bf[4][4];
            int kbB = kk * 32 + (((lane >> 3) & 1) << 4);
            int hB = kbB >> 7, wB = kbB & 127;
            #pragma unroll
            for (int g = 0; g < 4; g++) {
                int col = wc * 64 + g * 16 + (lane & 7) + (((lane >> 4) & 1) << 3);
                uint32_t bd = bbase + hB * 16384 + col * 128
                            + (wB ^ ((col & 7) << 4));
                LDSM4(bf[g], bd);
            }
            #pragma unroll
            for (int mi = 0; mi < 2; mi++)
                #pragma unroll
                for (int g = 0; g < 4; g++) {
                    MMA(acc[mi][2 * g],     af[mi], bf[g][0], bf[g][1]);
                    MMA(acc[mi][2 * g + 1], af[mi], bf[g][2], bf[g][3]);
                }
        }

        // ---- epilogue: fold 32x64 distances into per-row stats ----
        #pragma unroll
        for (int mi = 0; mi < 2; mi++)
            #pragma unroll
            for (int ni = 0; ni < 8; ni++)
                #pragma unroll
                for (int v = 0; v < 4; v++) {
                    int slot = mi * 2 + (v >> 1);
                    int cl   = wc * 64 + ni * 8 + (lane & 3) * 2 + (v & 1);
                    float2 st = stage[cl];
                    int cg = j0 + cl;
                    float d2 = fmaxf(fmaf(-2.0f, acc[mi][ni][v], sqi[slot] + st.x),
                                     1e-12f);
                    bool same = (__float_as_int(st.y) == tgi[slot]);
                    if (same) {
                        if (cg != rowg[slot]) {
                            ps[slot] += d2;
                            pmax[slot] = fmaxf(pmax[slot], d2);
                        }
                    } else {
                        ns[slot] += d2;
                        nmin[slot] = fminf(nmin[slot], d2);
                    }
                }
        __syncthreads();  // done reading buf c + stage
    }

    // ---- reduce across the 4 lanes sharing each row, write partials ----
    #pragma unroll
    for (int q = 0; q < 4; q++) {
        float a = ps[q], b = pmax[q], cn = ns[q], d = nmin[q];
        #pragma unroll
        for (int o = 1; o <= 2; o <<= 1) {
            a  += __shfl_xor_sync(0xffffffffu, a, o);
            b   = fmaxf(b, __shfl_xor_sync(0xffffffffu, b, o));
            cn += __shfl_xor_sync(0xffffffffu, cn, o);
            d   = fminf(d, __shfl_xor_sync(0xffffffffu, d, o));
        }
        if ((lane & 3) == 0)
            g_part[(half * 2 + wc) * N + rowg[q]] = make_float4(a, b, cn, d);
    }
}

// ---------------------------------------------------------------------------
// Hinge per row (parallel), block partial sums.
// ---------------------------------------------------------------------------
__global__ void hinge_kernel() {
    __shared__ float smr[256];
    int row = blockIdx.x * 256 + threadIdx.x;
    float4 p0 = g_part[row];
    float4 p1 = g_part[N + row];
    float4 p2 = g_part[2 * N + row];
    float4 p3 = g_part[3 * N + row];
    float psum = p0.x + p1.x + p2.x + p3.x;
    float pmax = fmaxf(fmaxf(p0.y, p1.y), fmaxf(p2.y, p3.y));
    float nsum = p0.z + p1.z + p2.z + p3.z;
    float nmin = fminf(fminf(p0.w, p1.w), fminf(p2.w, p3.w));
    int tg = __float_as_int(g_sqtg[row].y);
    int cc = g_cc[tg];
    float sp = psum / (float)(cc - 1);
    float ap = pmax / sp + 0.5f * logf(sp);
    float sn = nsum / (float)(N - cc);
    float an = nmin / sn + 0.5f * logf(sn);
    float h = fmaxf(ap - an + MARGIN, 0.0f);

    smr[threadIdx.x] = h;
    __syncthreads();
    for (int o = 128; o > 0; o >>= 1) {
        if (threadIdx.x < o) smr[threadIdx.x] += smr[threadIdx.x + o];
        __syncthreads();
    }
    if (threadIdx.x == 0) g_bsum[blockIdx.x] = smr[0];
}

__global__ void sum_kernel(float* __restrict__ out) {
    float v = g_bsum[threadIdx.x];
    #pragma unroll
    for (int o = 16; o > 0; o >>= 1) v += __shfl_xor_sync(0xffffffffu, v, o);
    if (threadIdx.x == 0) out[0] = v / (float)N;
}

extern "C" void kernel_launch(void* const* d_in, const int* in_sizes, int n_in,
                              void* d_out, int out_size) {
    (void)in_sizes; (void)n_in; (void)out_size;
    const float* x   = (const float*)d_in[0];
    const void*  tgt = d_in[1];

    detect_kernel<<<1, 256>>>((const unsigned int*)tgt);
    prep_kernel<<<128, 256>>>(x, tgt);

    cudaFuncSetAttribute(main_kernel, cudaFuncAttributeMaxDynamicSharedMemorySize, SMEM_REQ);
    main_kernel<<<128, 256, SMEM_REQ>>>();

    hinge_kernel<<<32, 256>>>();
    sum_kernel<<<1, 32>>>((float*)d_out);
}

// round 11
// speedup vs baseline: 2.2429x; 1.0683x over previous
#include <cuda_runtime.h>
#include <cuda_fp16.h>
#include <cstdint>

#define N 8192
#define D 128
#define MARGIN 0.3f
#define NCLS 256
#define FINF __int_as_float(0x7f800000)

__device__ __half  g_xh[N * D];         // fp16 inputs
__device__ float2  g_sqtg[N];           // (sq_norm fp32, target-as-bits)
__device__ int     g_cc[NCLS];
__device__ int     g_is64;
__device__ float4  g_part[4 * N];       // per (half, wc) partial stats
__device__ float   g_bsum[32];
__device__ int     g_done;              // last-block ticket (self-resetting)

// ---------------- PTX helpers ----------------
__device__ __forceinline__ uint32_t smem_u32(const void* p) {
    uint32_t a;
    asm("{ .reg .u64 t; cvta.to.shared.u64 t, %1; cvt.u32.u64 %0, t; }"
        : "=r"(a) : "l"(p));
    return a;
}
#define CP16(dst, src) \
    asm volatile("cp.async.cg.shared.global [%0], [%1], 16;" \
        :: "r"(dst), "l"(src) : "memory")
#define CP_COMMIT() asm volatile("cp.async.commit_group;" ::: "memory")
#define CP_WAIT(n)  asm volatile("cp.async.wait_group %0;" :: "n"(n) : "memory")

#define LDSM4(r, a) \
    asm volatile("ldmatrix.sync.aligned.m8n8.x4.shared.b16 {%0,%1,%2,%3}, [%4];" \
        : "=r"((r)[0]), "=r"((r)[1]), "=r"((r)[2]), "=r"((r)[3]) : "r"(a))

#define MMA(c, a, b0_, b1_) \
    asm volatile("mma.sync.aligned.m16n8k16.row.col.f32.f16.f16.f32 " \
        "{%0,%1,%2,%3},{%4,%5,%6,%7},{%8,%9},{%0,%1,%2,%3};" \
        : "+f"((c)[0]), "+f"((c)[1]), "+f"((c)[2]), "+f"((c)[3]) \
        : "r"((a)[0]), "r"((a)[1]), "r"((a)[2]), "r"((a)[3]), "r"(b0_), "r"(b1_))

// SMEM layout: 32KB A, 3x32KB B, 2KB stage (double-buffered)
#define OFF_A     0
#define OFF_B     32768
#define OFF_STAGE 131072
#define SMEM_REQ  (131072 + 2048)

// ---------------------------------------------------------------------------
__global__ void detect_kernel(const unsigned int* __restrict__ t) {
    __shared__ unsigned int sred[256];
    unsigned int acc = 0;
    for (int i = threadIdx.x; i < N / 2; i += 256) acc |= t[2 * i + 1];
    sred[threadIdx.x] = acc;
    __syncthreads();
    for (int s = 128; s > 0; s >>= 1) {
        if (threadIdx.x < s) sred[threadIdx.x] |= sred[threadIdx.x + s];
        __syncthreads();
    }
    if (threadIdx.x == 0) g_is64 = (sred[0] == 0u) ? 1 : 0;
    if (threadIdx.x < NCLS) g_cc[threadIdx.x] = 0;
}

// fp16 convert + fp32 norms + targets + class histogram.
__global__ void prep_kernel(const float* __restrict__ x, const void* __restrict__ tgt) {
    int lane = threadIdx.x & 31;
    int gw   = (blockIdx.x * 8) + (threadIdx.x >> 5);  // 0..1023
    const float4* X4 = (const float4*)x;
    uint2* OH = (uint2*)g_xh;
    int is64 = g_is64;

    #pragma unroll
    for (int r = 0; r < 8; r++) {
        int row = gw * 8 + r;
        float4 v = X4[row * 32 + lane];

        __half2 p01 = __floats2half2_rn(v.x, v.y);
        __half2 p23 = __floats2half2_rn(v.z, v.w);
        OH[row * 32 + lane] = make_uint2(*(uint32_t*)&p01, *(uint32_t*)&p23);

        float s = v.x * v.x + v.y * v.y + v.z * v.z + v.w * v.w;
        #pragma unroll
        for (int o = 16; o > 0; o >>= 1) s += __shfl_xor_sync(0xffffffffu, s, o);
        if (lane == 0) {
            int tg;
            if (is64) tg = (int)((const long long*)tgt)[row];
            else      tg = ((const int*)tgt)[row];
            g_sqtg[row] = make_float2(s, __int_as_float(tg));
            atomicAdd(&g_cc[tg], 1);
        }
    }
}

// ---------------------------------------------------------------------------
// Main: fp16 mma.sync distance GEMM + fused per-row stats.
// Triple-buffered B, ONE barrier per chunk:
//   CP_WAIT(chunk c) -> stage[c&1] write -> BAR -> prefetch c+2 -> compute c.
// Epilogue reads stage as float4, one load per ni reused across both mi.
// ---------------------------------------------------------------------------
__global__ void __launch_bounds__(256, 1) main_kernel() {
    extern __shared__ __align__(1024) char smraw[];
    uint32_t sb = smem_u32(smraw);

    int tid  = threadIdx.x;
    int lane = tid & 31;
    int wid  = tid >> 5;
    int wr   = wid >> 1;          // row group (32 rows)
    int wc   = wid & 1;           // col group (64 cols)
    int i0   = (blockIdx.x >> 1) * 128;
    int half = blockIdx.x & 1;
    int jb   = half * 4096;

    // ---- A tile + B chunk 0 (one group) ----
    #pragma unroll
    for (int t = 0; t < 8; t++) {
        int idx = tid + t * 256;
        int r   = idx >> 4;
        int kc  = idx & 15;
        uint32_t so = (kc >> 3) * 16384 + r * 128 + (((kc & 7) << 4) ^ ((r & 7) << 4));
        CP16(sb + OFF_A + so, g_xh + (i0 + r) * D + kc * 8);
        CP16(sb + OFF_B + so, g_xh + (jb + r) * D + kc * 8);
    }
    CP_COMMIT();
    // ---- B chunk 1 ----
    #pragma unroll
    for (int t = 0; t < 8; t++) {
        int idx = tid + t * 256;
        int r   = idx >> 4;
        int kc  = idx & 15;
        uint32_t so = (kc >> 3) * 16384 + r * 128 + (((kc & 7) << 4) ^ ((r & 7) << 4));
        CP16(sb + OFF_B + 32768 + so, g_xh + (jb + 128 + r) * D + kc * 8);
    }
    CP_COMMIT();

    // ---- per-thread stats for 4 fixed rows ----
    float ps[4], pmax[4], ns[4], nmin[4], sqi[4];
    int tgi[4], rowg[4];
    #pragma unroll
    for (int q = 0; q < 4; q++) {
        rowg[q] = i0 + wr * 32 + q * 8 + (lane >> 2);
        float2 st = g_sqtg[rowg[q]];
        sqi[q] = st.x;
        tgi[q] = __float_as_int(st.y);
        ps[q] = 0.0f; ns[q] = 0.0f; pmax[q] = -FINF; nmin[q] = FINF;
    }
    int colbase = wc * 64 + (lane & 3) * 2;

    int bcur = 0;  // c % 3
    for (int c = 0; c < 32; c++) {
        int j0 = jb + c * 128;

        if (c < 31) { CP_WAIT(1); } else { CP_WAIT(0); }
        // stage chunk c metadata (parity buffer; other parity may still be read)
        if (tid < 128)
            *((float2*)(smraw + OFF_STAGE) + (c & 1) * 128 + tid) = g_sqtg[j0 + tid];
        __syncthreads();  // B chunk c + stage visible; epilogue c-1 done everywhere

        // prefetch chunk c+2 into the buffer epilogue c-1 released
        if (c < 30) {
            int bn = bcur + 2; if (bn >= 3) bn -= 3;
            int jn = jb + (c + 2) * 128;
            uint32_t bdst = sb + OFF_B + bn * 32768;
            #pragma unroll
            for (int t = 0; t < 8; t++) {
                int idx = tid + t * 256;
                int r   = idx >> 4;
                int kc  = idx & 15;
                uint32_t so = (kc >> 3) * 16384 + r * 128
                            + (((kc & 7) << 4) ^ ((r & 7) << 4));
                CP16(bdst + so, g_xh + (jn + r) * D + kc * 8);
            }
            CP_COMMIT();
        }

        // ---- compute 128x128 (this warp: 32x64), single fp16 term ----
        float acc[2][8][4];
        #pragma unroll
        for (int mi = 0; mi < 2; mi++)
            #pragma unroll
            for (int ni = 0; ni < 8; ni++)
                #pragma unroll
                for (int v = 0; v < 4; v++) acc[mi][ni][v] = 0.0f;

        uint32_t bbase = sb + OFF_B + bcur * 32768;
        uint32_t abase = sb + OFF_A;
        #pragma unroll
        for (int kk = 0; kk < 8; kk++) {
            uint32_t af[2][4];
            int kbA = kk * 32 + ((lane >> 4) << 4);
            int hA = kbA >> 7, wA = kbA & 127;
            #pragma unroll
            for (int mi = 0; mi < 2; mi++) {
                int row = wr * 32 + mi * 16 + (lane & 15);
                uint32_t ad = abase + hA * 16384 + row * 128
                            + (wA ^ ((row & 7) << 4));
                LDSM4(af[mi], ad);
            }
            uint32_t bf[4][4];
            int kbB = kk * 32 + (((lane >> 3) & 1) << 4);
            int hB = kbB >> 7, wB = kbB & 127;
            #pragma unroll
            for (int g = 0; g < 4; g++) {
                int col = wc * 64 + g * 16 + (lane & 7) + (((lane >> 4) & 1) << 3);
                uint32_t bd = bbase + hB * 16384 + col * 128
                            + (wB ^ ((col & 7) << 4));
                LDSM4(bf[g], bd);
            }
            #pragma unroll
            for (int mi = 0; mi < 2; mi++)
                #pragma unroll
                for (int g = 0; g < 4; g++) {
                    MMA(acc[mi][2 * g],     af[mi], bf[g][0], bf[g][1]);
                    MMA(acc[mi][2 * g + 1], af[mi], bf[g][2], bf[g][3]);
                }
        }

        // ---- epilogue: one float4 stage read per ni, reused across mi ----
        const float4* stage4 =
            (const float4*)(smraw + OFF_STAGE + (c & 1) * 1024);
        #pragma unroll
        for (int ni = 0; ni < 8; ni++) {
            float4 sv = stage4[(colbase >> 1) + ni * 4];
            #pragma unroll
            for (int mi = 0; mi < 2; mi++)
                #pragma unroll
                for (int v = 0; v < 4; v++) {
                    int slot = mi * 2 + (v >> 1);
                    int b    = v & 1;
                    float sqj = b ? sv.z : sv.x;
                    int   tgj = __float_as_int(b ? sv.w : sv.y);
                    int cl = colbase + ni * 8 + b;
                    float d2 = fmaxf(fmaf(-2.0f, acc[mi][ni][v], sqi[slot] + sqj),
                                     1e-12f);
                    if (tgj == tgi[slot]) {
                        if (j0 + cl != rowg[slot]) {
                            ps[slot] += d2;
                            pmax[slot] = fmaxf(pmax[slot], d2);
                        }
                    } else {
                        ns[slot] += d2;
                        nmin[slot] = fminf(nmin[slot], d2);
                    }
                }
        }

        bcur++; if (bcur >= 3) bcur -= 3;
    }

    // ---- reduce across the 4 lanes sharing each row, write partials ----
    #pragma unroll
    for (int q = 0; q < 4; q++) {
        float a = ps[q], b = pmax[q], cn = ns[q], d = nmin[q];
        #pragma unroll
        for (int o = 1; o <= 2; o <<= 1) {
            a  += __shfl_xor_sync(0xffffffffu, a, o);
            b   = fmaxf(b, __shfl_xor_sync(0xffffffffu, b, o));
            cn += __shfl_xor_sync(0xffffffffu, cn, o);
            d   = fminf(d, __shfl_xor_sync(0xffffffffu, d, o));
        }
        if ((lane & 3) == 0)
            g_part[(half * 2 + wc) * N + rowg[q]] = make_float4(a, b, cn, d);
    }
}

// ---------------------------------------------------------------------------
// Hinge per row + fused final sum (last-block-done pattern; deterministic).
// ---------------------------------------------------------------------------
__global__ void hinge_kernel(float* __restrict__ out) {
    __shared__ float smr[256];
    __shared__ int last;
    int row = blockIdx.x * 256 + threadIdx.x;
    float4 p0 = g_part[row];
    float4 p1 = g_part[N + row];
    float4 p2 = g_part[2 * N + row];
    float4 p3 = g_part[3 * N + row];
    float psum = p0.x + p1.x + p2.x + p3.x;
    float pmax = fmaxf(fmaxf(p0.y, p1.y), fmaxf(p2.y, p3.y));
    float nsum = p0.z + p1.z + p2.z + p3.z;
    float nmin = fminf(fminf(p0.w, p1.w), fminf(p2.w, p3.w));
    int tg = __float_as_int(g_sqtg[row].y);
    int cc = g_cc[tg];
    float sp = psum / (float)(cc - 1);
    float ap = pmax / sp + 0.5f * logf(sp);
    float sn = nsum / (float)(N - cc);
    float an = nmin / sn + 0.5f * logf(sn);
    float h = fmaxf(ap - an + MARGIN, 0.0f);

    smr[threadIdx.x] = h;
    __syncthreads();
    for (int o = 128; o > 0; o >>= 1) {
        if (threadIdx.x < o) smr[threadIdx.x] += smr[threadIdx.x + o];
        __syncthreads();
    }
    if (threadIdx.x == 0) {
        g_bsum[blockIdx.x] = smr[0];
        __threadfence();
        int t = atomicAdd(&g_done, 1);
        last = (t == 31);
    }
    __syncthreads();
    if (last && threadIdx.x < 32) {
        __threadfence();
        float v = ((volatile float*)g_bsum)[threadIdx.x];
        #pragma unroll
        for (int o = 16; o > 0; o >>= 1) v += __shfl_xor_sync(0xffffffffu, v, o);
        if (threadIdx.x == 0) {
            out[0] = v / (float)N;
            g_done = 0;  // reset for next (graph-replayed) launch
        }
    }
}

extern "C" void kernel_launch(void* const* d_in, const int* in_sizes, int n_in,
                              void* d_out, int out_size) {
    (void)in_sizes; (void)n_in; (void)out_size;
    const float* x   = (const float*)d_in[0];
    const void*  tgt = d_in[1];

    detect_kernel<<<1, 256>>>((const unsigned int*)tgt);
    prep_kernel<<<128, 256>>>(x, tgt);

    cudaFuncSetAttribute(main_kernel, cudaFuncAttributeMaxDynamicSharedMemorySize, SMEM_REQ);
    main_kernel<<<128, 256, SMEM_REQ>>>();

    hinge_kernel<<<32, 256>>>((float*)d_out);
}

// round 12
// speedup vs baseline: 2.6552x; 1.1838x over previous
#include <cuda_runtime.h>
#include <cuda_fp16.h>
#include <cstdint>

#define N 8192
#define D 128
#define MARGIN 0.3f
#define NCLS 256
#define FINF __int_as_float(0x7f800000)

__device__ __half  g_xh[N * D];         // fp16 inputs
__device__ float2  g_sqtg[N];           // (sq_norm fp32, target-as-bits)
__device__ int     g_cc[NCLS];
__device__ int     g_is64;
__device__ float   g_ps[N];             // pos sum
__device__ int     g_pm[N];             // pos max (float bits, >=0)
__device__ float   g_ns[N];             // neg sum
__device__ int     g_nm[N];             // neg min (float bits, >=0)
__device__ float   g_bsum[32];
__device__ int     g_done;              // last-block ticket (self-resetting)

// ---------------- PTX helpers ----------------
__device__ __forceinline__ uint32_t smem_u32(const void* p) {
    uint32_t a;
    asm("{ .reg .u64 t; cvta.to.shared.u64 t, %1; cvt.u32.u64 %0, t; }"
        : "=r"(a) : "l"(p));
    return a;
}
#define CP16(dst, src) \
    asm volatile("cp.async.cg.shared.global [%0], [%1], 16;" \
        :: "r"(dst), "l"(src) : "memory")
#define CP_COMMIT() asm volatile("cp.async.commit_group;" ::: "memory")
#define CP_WAIT(n)  asm volatile("cp.async.wait_group %0;" :: "n"(n) : "memory")

#define LDSM4(r, a) \
    asm volatile("ldmatrix.sync.aligned.m8n8.x4.shared.b16 {%0,%1,%2,%3}, [%4];" \
        : "=r"((r)[0]), "=r"((r)[1]), "=r"((r)[2]), "=r"((r)[3]) : "r"(a))

#define MMA(c, a, b0_, b1_) \
    asm volatile("mma.sync.aligned.m16n8k16.row.col.f32.f16.f16.f32 " \
        "{%0,%1,%2,%3},{%4,%5,%6,%7},{%8,%9},{%0,%1,%2,%3};" \
        : "+f"((c)[0]), "+f"((c)[1]), "+f"((c)[2]), "+f"((c)[3]) \
        : "r"((a)[0]), "r"((a)[1]), "r"((a)[2]), "r"((a)[3]), "r"(b0_), "r"(b1_))

// SMEM: 32KB A, 3x32KB B, 2KB stage, 8KB scol
#define OFF_A     0
#define OFF_B     32768
#define OFF_STAGE 131072
#define OFF_SCOL  133120
#define SMEM_REQ  (133120 + 8192)

// ---------------------------------------------------------------------------
__global__ void detect_kernel(const unsigned int* __restrict__ t) {
    __shared__ unsigned int sred[256];
    unsigned int acc = 0;
    for (int i = threadIdx.x; i < N / 2; i += 256) acc |= t[2 * i + 1];
    sred[threadIdx.x] = acc;
    __syncthreads();
    for (int s = 128; s > 0; s >>= 1) {
        if (threadIdx.x < s) sred[threadIdx.x] |= sred[threadIdx.x + s];
        __syncthreads();
    }
    if (threadIdx.x == 0) g_is64 = (sred[0] == 0u) ? 1 : 0;
    if (threadIdx.x < NCLS) g_cc[threadIdx.x] = 0;
}

// fp16 convert + fp32 norms + targets + histogram + stat-array init.
__global__ void prep_kernel(const float* __restrict__ x, const void* __restrict__ tgt) {
    int lane = threadIdx.x & 31;
    int gw   = (blockIdx.x * 8) + (threadIdx.x >> 5);
    const float4* X4 = (const float4*)x;
    uint2* OH = (uint2*)g_xh;
    int is64 = g_is64;

    #pragma unroll
    for (int r = 0; r < 8; r++) {
        int row = gw * 8 + r;
        float4 v = X4[row * 32 + lane];

        __half2 p01 = __floats2half2_rn(v.x, v.y);
        __half2 p23 = __floats2half2_rn(v.z, v.w);
        OH[row * 32 + lane] = make_uint2(*(uint32_t*)&p01, *(uint32_t*)&p23);

        float s = v.x * v.x + v.y * v.y + v.z * v.z + v.w * v.w;
        #pragma unroll
        for (int o = 16; o > 0; o >>= 1) s += __shfl_xor_sync(0xffffffffu, s, o);
        if (lane == 0) {
            int tg;
            if (is64) tg = (int)((const long long*)tgt)[row];
            else      tg = ((const int*)tgt)[row];
            g_sqtg[row] = make_float2(s, __int_as_float(tg));
            atomicAdd(&g_cc[tg], 1);
            g_ps[row] = 0.0f; g_ns[row] = 0.0f;
            g_pm[row] = 0;    g_nm[row] = 0x7f800000;
        }
    }
}

// ---------------------------------------------------------------------------
// Main: symmetric (circulant) fp16 mma.sync distance GEMM + fused stats.
// Block (ti = blockIdx/2, h = blockIdx&1) handles j-tiles d = h, h+2 ... dmax
// (dmax = ti<32 ? 32 : 31, tj = (ti+d)&63): each unordered tile pair once.
// Off-diagonal chunks also harvest column stats for tj via shfl+smem+atomics.
// ---------------------------------------------------------------------------
__global__ void __launch_bounds__(256, 1) main_kernel() {
    extern __shared__ __align__(1024) char smraw[];
    uint32_t sb = smem_u32(smraw);
    float* scol = (float*)(smraw + OFF_SCOL);          // [wr][col][stat]

    int tid  = threadIdx.x;
    int lane = tid & 31;
    int wid  = tid >> 5;
    int wr   = wid >> 1;
    int wc   = wid & 1;
    int ti   = blockIdx.x >> 1;
    int hk   = blockIdx.x & 1;
    int i0   = ti * 128;
    int dmax = (ti < 32) ? 32 : 31;
    int nc   = ((dmax - hk) >> 1) + 1;                 // 16 or 17 chunks

    // ---- A tile + B chunk 0 ----
    {
        int j00 = ((ti + hk) & 63) * 128;
        #pragma unroll
        for (int t = 0; t < 8; t++) {
            int idx = tid + t * 256;
            int r   = idx >> 4;
            int kc  = idx & 15;
            uint32_t so = (kc >> 3) * 16384 + r * 128
                        + (((kc & 7) << 4) ^ ((r & 7) << 4));
            CP16(sb + OFF_A + so, g_xh + (i0 + r) * D + kc * 8);
            CP16(sb + OFF_B + so, g_xh + (j00 + r) * D + kc * 8);
        }
        CP_COMMIT();
    }
    // ---- B chunk 1 ----
    {
        int j01 = ((ti + hk + 2) & 63) * 128;
        #pragma unroll
        for (int t = 0; t < 8; t++) {
            int idx = tid + t * 256;
            int r   = idx >> 4;
            int kc  = idx & 15;
            uint32_t so = (kc >> 3) * 16384 + r * 128
                        + (((kc & 7) << 4) ^ ((r & 7) << 4));
            CP16(sb + OFF_B + 32768 + so, g_xh + (j01 + r) * D + kc * 8);
        }
        CP_COMMIT();
    }

    // ---- per-thread stats for 4 fixed rows (registers across all chunks) ----
    float ps[4], pmax[4], ns[4], nmin[4], sqi[4];
    int tgi[4], rowg[4];
    #pragma unroll
    for (int q = 0; q < 4; q++) {
        rowg[q] = i0 + wr * 32 + q * 8 + (lane >> 2);
        float2 st = g_sqtg[rowg[q]];
        sqi[q] = st.x;
        tgi[q] = __float_as_int(st.y);
        ps[q] = 0.0f; ns[q] = 0.0f; pmax[q] = -FINF; nmin[q] = FINF;
    }
    int colbase = wc * 64 + (lane & 3) * 2;

    int bcur = 0;
    for (int c = 0; c < nc; c++) {
        int d  = hk + 2 * c;
        int j0 = ((ti + d) & 63) * 128;

        if (c < nc - 1) { CP_WAIT(1); } else { CP_WAIT(0); }
        if (tid < 128)
            *((float2*)(smraw + OFF_STAGE) + (c & 1) * 128 + tid) = g_sqtg[j0 + tid];
        __syncthreads();

        // prefetch chunk c+2
        if (c + 2 < nc) {
            int bn = bcur + 2; if (bn >= 3) bn -= 3;
            int jn = ((ti + d + 4) & 63) * 128;
            uint32_t bdst = sb + OFF_B + bn * 32768;
            #pragma unroll
            for (int t = 0; t < 8; t++) {
                int idx = tid + t * 256;
                int r   = idx >> 4;
                int kc  = idx & 15;
                uint32_t so = (kc >> 3) * 16384 + r * 128
                            + (((kc & 7) << 4) ^ ((r & 7) << 4));
                CP16(bdst + so, g_xh + (jn + r) * D + kc * 8);
            }
            CP_COMMIT();
        }

        // ---- compute 128x128 (this warp: 32x64) ----
        float acc[2][8][4];
        #pragma unroll
        for (int mi = 0; mi < 2; mi++)
            #pragma unroll
            for (int ni = 0; ni < 8; ni++)
                #pragma unroll
                for (int v = 0; v < 4; v++) acc[mi][ni][v] = 0.0f;

        uint32_t bbase = sb + OFF_B + bcur * 32768;
        uint32_t abase = sb + OFF_A;
        #pragma unroll
        for (int kk = 0; kk < 8; kk++) {
            uint32_t af[2][4];
            int kbA = kk * 32 + ((lane >> 4) << 4);
            int hA = kbA >> 7, wA = kbA & 127;
            #pragma unroll
            for (int mi = 0; mi < 2; mi++) {
                int row = wr * 32 + mi * 16 + (lane & 15);
                uint32_t ad = abase + hA * 16384 + row * 128
                            + (wA ^ ((row & 7) << 4));
                LDSM4(af[mi], ad);
            }
            uint32_t bf[4][4];
            int kbB = kk * 32 + (((lane >> 3) & 1) << 4);
            int hB = kbB >> 7, wB = kbB & 127;
            #pragma unroll
            for (int g = 0; g < 4; g++) {
                int col = wc * 64 + g * 16 + (lane & 7) + (((lane >> 4) & 1) << 3);
                uint32_t bd = bbase + hB * 16384 + col * 128
                            + (wB ^ ((col & 7) << 4));
                LDSM4(bf[g], bd);
            }
            #pragma unroll
            for (int mi = 0; mi < 2; mi++)
                #pragma unroll
                for (int g = 0; g < 4; g++) {
                    MMA(acc[mi][2 * g],     af[mi], bf[g][0], bf[g][1]);
                    MMA(acc[mi][2 * g + 1], af[mi], bf[g][2], bf[g][3]);
                }
        }

        const float4* stage4 = (const float4*)(smraw + OFF_STAGE + (c & 1) * 1024);

        if (d == 0) {
            // ---- diagonal: row stats only, self-exclusion ----
            #pragma unroll
            for (int ni = 0; ni < 8; ni++) {
                float4 sv = stage4[(colbase >> 1) + ni * 4];
                #pragma unroll
                for (int mi = 0; mi < 2; mi++)
                    #pragma unroll
                    for (int v = 0; v < 4; v++) {
                        int slot = mi * 2 + (v >> 1);
                        int b    = v & 1;
                        float sqj = b ? sv.z : sv.x;
                        int   tgj = __float_as_int(b ? sv.w : sv.y);
                        int cl = colbase + ni * 8 + b;
                        float d2 = fmaxf(fmaf(-2.0f, acc[mi][ni][v],
                                              sqi[slot] + sqj), 1e-12f);
                        if (tgj == tgi[slot]) {
                            if (j0 + cl != rowg[slot]) {
                                ps[slot] += d2;
                                pmax[slot] = fmaxf(pmax[slot], d2);
                            }
                        } else {
                            ns[slot] += d2;
                            nmin[slot] = fminf(nmin[slot], d2);
                        }
                    }
            }
        } else {
            // ---- off-diagonal: row stats + column stats ----
            #pragma unroll
            for (int ni = 0; ni < 8; ni++) {
                float4 sv = stage4[(colbase >> 1) + ni * 4];
                float cps0 = 0.0f, cpm0 = 0.0f, cns0 = 0.0f, cnm0 = FINF;
                float cps1 = 0.0f, cpm1 = 0.0f, cns1 = 0.0f, cnm1 = FINF;
                #pragma unroll
                for (int mi = 0; mi < 2; mi++)
                    #pragma unroll
                    for (int hv = 0; hv < 2; hv++) {
                        int slot = mi * 2 + hv;
                        float d20 = fmaxf(fmaf(-2.0f, acc[mi][ni][hv * 2],
                                               sqi[slot] + sv.x), 1e-12f);
                        if (__float_as_int(sv.y) == tgi[slot]) {
                            ps[slot] += d20; pmax[slot] = fmaxf(pmax[slot], d20);
                            cps0 += d20; cpm0 = fmaxf(cpm0, d20);
                        } else {
                            ns[slot] += d20; nmin[slot] = fminf(nmin[slot], d20);
                            cns0 += d20; cnm0 = fminf(cnm0, d20);
                        }
                        float d21 = fmaxf(fmaf(-2.0f, acc[mi][ni][hv * 2 + 1],
                                               sqi[slot] + sv.z), 1e-12f);
                        if (__float_as_int(sv.w) == tgi[slot]) {
                            ps[slot] += d21; pmax[slot] = fmaxf(pmax[slot], d21);
                            cps1 += d21; cpm1 = fmaxf(cpm1, d21);
                        } else {
                            ns[slot] += d21; nmin[slot] = fminf(nmin[slot], d21);
                            cns1 += d21; cnm1 = fminf(cnm1, d21);
                        }
                    }
                // reduce col stats over the 8 row-lanes (xor 4,8,16)
                #pragma unroll
                for (int o = 4; o <= 16; o <<= 1) {
                    cps0 += __shfl_xor_sync(0xffffffffu, cps0, o);
                    cpm0 = fmaxf(cpm0, __shfl_xor_sync(0xffffffffu, cpm0, o));
                    cns0 += __shfl_xor_sync(0xffffffffu, cns0, o);
                    cnm0 = fminf(cnm0, __shfl_xor_sync(0xffffffffu, cnm0, o));
                    cps1 += __shfl_xor_sync(0xffffffffu, cps1, o);
                    cpm1 = fmaxf(cpm1, __shfl_xor_sync(0xffffffffu, cpm1, o));
                    cns1 += __shfl_xor_sync(0xffffffffu, cns1, o);
                    cnm1 = fminf(cnm1, __shfl_xor_sync(0xffffffffu, cnm1, o));
                }
                // 32 lanes write 4 stats x 2 cols: stat=(lane>>2)&3, b=lane>>4
                int stat = (lane >> 2) & 3;
                int b    = lane >> 4;
                float v0 = b ? ((stat & 2) ? ((stat & 1) ? cnm1 : cns1)
                                           : ((stat & 1) ? cpm1 : cps1))
                             : ((stat & 2) ? ((stat & 1) ? cnm0 : cns0)
                                           : ((stat & 1) ? cpm0 : cps0));
                int col = colbase + ni * 8 + b;
                scol[wr * 512 + col * 4 + stat] = v0;
            }
            __syncthreads();
            if (tid < 128) {
                const float4* sc = (const float4*)scol;
                float4 s0 = sc[tid], s1 = sc[128 + tid];
                float4 s2 = sc[256 + tid], s3 = sc[384 + tid];
                float aps = s0.x + s1.x + s2.x + s3.x;
                float apm = fmaxf(fmaxf(s0.y, s1.y), fmaxf(s2.y, s3.y));
                float ans = s0.z + s1.z + s2.z + s3.z;
                float anm = fminf(fminf(s0.w, s1.w), fminf(s2.w, s3.w));
                int row = j0 + tid;
                atomicAdd(&g_ps[row], aps);
                atomicMax(&g_pm[row], __float_as_int(apm));
                atomicAdd(&g_ns[row], ans);
                atomicMin(&g_nm[row], __float_as_int(anm));
            }
        }

        bcur++; if (bcur >= 3) bcur -= 3;
    }

    // ---- merge this block's register row stats ----
    #pragma unroll
    for (int q = 0; q < 4; q++) {
        float a = ps[q], b = pmax[q], cn = ns[q], dd = nmin[q];
        #pragma unroll
        for (int o = 1; o <= 2; o <<= 1) {
            a  += __shfl_xor_sync(0xffffffffu, a, o);
            b   = fmaxf(b, __shfl_xor_sync(0xffffffffu, b, o));
            cn += __shfl_xor_sync(0xffffffffu, cn, o);
            dd  = fminf(dd, __shfl_xor_sync(0xffffffffu, dd, o));
        }
        if ((lane & 3) == 0) {
            int row = rowg[q];
            atomicAdd(&g_ps[row], a);
            atomicMax(&g_pm[row], __float_as_int(b));
            atomicAdd(&g_ns[row], cn);
            atomicMin(&g_nm[row], __float_as_int(dd));
        }
    }
}

// ---------------------------------------------------------------------------
// Hinge per row + fused final sum (last-block-done pattern).
// ---------------------------------------------------------------------------
__global__ void hinge_kernel(float* __restrict__ out) {
    __shared__ float smr[256];
    __shared__ int last;
    int row = blockIdx.x * 256 + threadIdx.x;
    float psum = g_ps[row];
    float pmax = __int_as_float(g_pm[row]);
    float nsum = g_ns[row];
    float nmin = __int_as_float(g_nm[row]);
    int tg = __float_as_int(g_sqtg[row].y);
    int cc = g_cc[tg];
    float sp = psum / (float)(cc - 1);
    float ap = pmax / sp + 0.5f * logf(sp);
    float sn = nsum / (float)(N - cc);
    float an = nmin / sn + 0.5f * logf(sn);
    float h = fmaxf(ap - an + MARGIN, 0.0f);

    smr[threadIdx.x] = h;
    __syncthreads();
    for (int o = 128; o > 0; o >>= 1) {
        if (threadIdx.x < o) smr[threadIdx.x] += smr[threadIdx.x + o];
        __syncthreads();
    }
    if (threadIdx.x == 0) {
        g_bsum[blockIdx.x] = smr[0];
        __threadfence();
        int t = atomicAdd(&g_done, 1);
        last = (t == 31);
    }
    __syncthreads();
    if (last && threadIdx.x < 32) {
        __threadfence();
        float v = ((volatile float*)g_bsum)[threadIdx.x];
        #pragma unroll
        for (int o = 16; o > 0; o >>= 1) v += __shfl_xor_sync(0xffffffffu, v, o);
        if (threadIdx.x == 0) {
            out[0] = v / (float)N;
            g_done = 0;
        }
    }
}

extern "C" void kernel_launch(void* const* d_in, const int* in_sizes, int n_in,
                              void* d_out, int out_size) {
    (void)in_sizes; (void)n_in; (void)out_size;
    const float* x   = (const float*)d_in[0];
    const void*  tgt = d_in[1];

    detect_kernel<<<1, 256>>>((const unsigned int*)tgt);
    prep_kernel<<<128, 256>>>(x, tgt);

    cudaFuncSetAttribute(main_kernel, cudaFuncAttributeMaxDynamicSharedMemorySize, SMEM_REQ);
    main_kernel<<<128, 256, SMEM_REQ>>>();

    hinge_kernel<<<32, 256>>>((float*)d_out);
}

// round 16
// speedup vs baseline: 2.6738x; 1.0070x over previous
#include <cuda_runtime.h>
#include <cuda_fp16.h>
#include <cstdint>

#define N 8192
#define D 128
#define MARGIN 0.3f
#define NCLS 256
#define FINF __int_as_float(0x7f800000)

__device__ __half  g_xh[N * D];         // fp16 inputs
__device__ float2  g_sqtg[N];           // (sq_norm fp32, target-as-bits)
__device__ int     g_cc[NCLS];
__device__ int     g_is64;
__device__ float   g_ps[N];             // pos sum
__device__ int     g_pm[N];             // pos max (float bits, >=0)
__device__ float   g_ns[N];             // neg sum
__device__ int     g_nm[N];             // neg min (float bits, >=0)
__device__ float   g_bsum[32];
__device__ int     g_done;              // last-block ticket (self-resetting)

// ---------------- PTX helpers ----------------
__device__ __forceinline__ uint32_t smem_u32(const void* p) {
    uint32_t a;
    asm("{ .reg .u64 t; cvta.to.shared.u64 t, %1; cvt.u32.u64 %0, t; }"
        : "=r"(a) : "l"(p));
    return a;
}
#define CP16(dst, src) \
    asm volatile("cp.async.cg.shared.global [%0], [%1], 16;" \
        :: "r"(dst), "l"(src) : "memory")
#define CP_COMMIT() asm volatile("cp.async.commit_group;" ::: "memory")
#define CP_WAIT(n)  asm volatile("cp.async.wait_group %0;" :: "n"(n) : "memory")

#define LDSM4(r, a) \
    asm volatile("ldmatrix.sync.aligned.m8n8.x4.shared.b16 {%0,%1,%2,%3}, [%4];" \
        : "=r"((r)[0]), "=r"((r)[1]), "=r"((r)[2]), "=r"((r)[3]) : "r"(a))

#define MMA(c, a, b0_, b1_) \
    asm volatile("mma.sync.aligned.m16n8k16.row.col.f32.f16.f16.f32 " \
        "{%0,%1,%2,%3},{%4,%5,%6,%7},{%8,%9},{%0,%1,%2,%3};" \
        : "+f"((c)[0]), "+f"((c)[1]), "+f"((c)[2]), "+f"((c)[3]) \
        : "r"((a)[0]), "r"((a)[1]), "r"((a)[2]), "r"((a)[3]), "r"(b0_), "r"(b1_))

// SMEM: 32KB A, 2x32KB B, 2KB stage, 8KB scol  (=108.5KB -> 2 CTAs/SM)
#define OFF_A     0
#define OFF_B     32768
#define OFF_STAGE 98304
#define OFF_SCOL  100352
#define SMEM_REQ  108544

// ---------------------------------------------------------------------------
__global__ void detect_kernel(const unsigned int* __restrict__ t) {
    __shared__ unsigned int sred[256];
    unsigned int acc = 0;
    for (int i = threadIdx.x; i < N / 2; i += 256) acc |= t[2 * i + 1];
    sred[threadIdx.x] = acc;
    __syncthreads();
    for (int s = 128; s > 0; s >>= 1) {
        if (threadIdx.x < s) sred[threadIdx.x] |= sred[threadIdx.x + s];
        __syncthreads();
    }
    if (threadIdx.x == 0) g_is64 = (sred[0] == 0u) ? 1 : 0;
    if (threadIdx.x < NCLS) g_cc[threadIdx.x] = 0;
}

// fp16 convert + fp32 norms + targets + histogram + stat-array init.
__global__ void prep_kernel(const float* __restrict__ x, const void* __restrict__ tgt) {
    int lane = threadIdx.x & 31;
    int gw   = (blockIdx.x * 8) + (threadIdx.x >> 5);
    const float4* X4 = (const float4*)x;
    uint2* OH = (uint2*)g_xh;
    int is64 = g_is64;

    #pragma unroll
    for (int r = 0; r < 8; r++) {
        int row = gw * 8 + r;
        float4 v = X4[row * 32 + lane];

        __half2 p01 = __floats2half2_rn(v.x, v.y);
        __half2 p23 = __floats2half2_rn(v.z, v.w);
        OH[row * 32 + lane] = make_uint2(*(uint32_t*)&p01, *(uint32_t*)&p23);

        float s = v.x * v.x + v.y * v.y + v.z * v.z + v.w * v.w;
        #pragma unroll
        for (int o = 16; o > 0; o >>= 1) s += __shfl_xor_sync(0xffffffffu, s, o);
        if (lane == 0) {
            int tg;
            if (is64) tg = (int)((const long long*)tgt)[row];
            else      tg = ((const int*)tgt)[row];
            g_sqtg[row] = make_float2(s, __int_as_float(tg));
            atomicAdd(&g_cc[tg], 1);
            g_ps[row] = 0.0f; g_ns[row] = 0.0f;
            g_pm[row] = 0;    g_nm[row] = 0x7f800000;
        }
    }
}

// ---------------------------------------------------------------------------
// Main: symmetric (circulant) fp16 mma.sync distance GEMM + fused stats.
// Occupancy 2 (double-buffered B): one CTA's MMA overlaps the other's
// epilogue/barriers. Schedule identical to R12.
// ---------------------------------------------------------------------------
__global__ void __launch_bounds__(256, 2) main_kernel() {
    extern __shared__ __align__(1024) char smraw[];
    uint32_t sb = smem_u32(smraw);
    float* scol = (float*)(smraw + OFF_SCOL);          // [wr][col][stat]

    int tid  = threadIdx.x;
    int lane = tid & 31;
    int wid  = tid >> 5;
    int wr   = wid >> 1;
    int wc   = wid & 1;
    int ti   = blockIdx.x >> 1;
    int hk   = blockIdx.x & 1;
    int i0   = ti * 128;
    int dmax = (ti < 32) ? 32 : 31;
    int nc   = ((dmax - hk) >> 1) + 1;                 // 16 or 17 chunks

    // ---- A tile + B chunk 0 (one cp.async group) ----
    {
        int j00 = ((ti + hk) & 63) * 128;
        #pragma unroll
        for (int t = 0; t < 8; t++) {
            int idx = tid + t * 256;
            int r   = idx >> 4;
            int kc  = idx & 15;
            uint32_t so = (kc >> 3) * 16384 + r * 128
                        + (((kc & 7) << 4) ^ ((r & 7) << 4));
            CP16(sb + OFF_A + so, g_xh + (i0 + r) * D + kc * 8);
            CP16(sb + OFF_B + so, g_xh + (j00 + r) * D + kc * 8);
        }
        CP_COMMIT();
    }

    // ---- per-thread stats for 4 fixed rows (registers across all chunks) ----
    float ps[4], pmax[4], ns[4], nmin[4], sqi[4];
    int tgi[4], rowg[4];
    #pragma unroll
    for (int q = 0; q < 4; q++) {
        rowg[q] = i0 + wr * 32 + q * 8 + (lane >> 2);
        float2 st = g_sqtg[rowg[q]];
        sqi[q] = st.x;
        tgi[q] = __float_as_int(st.y);
        ps[q] = 0.0f; ns[q] = 0.0f; pmax[q] = -FINF; nmin[q] = FINF;
    }
    int colbase = wc * 64 + (lane & 3) * 2;

    for (int c = 0; c < nc; c++) {
        int d  = hk + 2 * c;
        int j0 = ((ti + d) & 63) * 128;

        CP_WAIT(0);  // chunk c resident (only group outstanding)
        if (tid < 128)
            *((float2*)(smraw + OFF_STAGE) + (c & 1) * 128 + tid) = g_sqtg[j0 + tid];
        __syncthreads();  // B chunk c + stage visible; epilogue c-1 done

        // prefetch chunk c+1 into the other buffer (overlaps compute c)
        if (c + 1 < nc) {
            int jn = ((ti + d + 2) & 63) * 128;
            uint32_t bdst = sb + OFF_B + ((c + 1) & 1) * 32768;
            #pragma unroll
            for (int t = 0; t < 8; t++) {
                int idx = tid + t * 256;
                int r   = idx >> 4;
                int kc  = idx & 15;
                uint32_t so = (kc >> 3) * 16384 + r * 128
                            + (((kc & 7) << 4) ^ ((r & 7) << 4));
                CP16(bdst + so, g_xh + (jn + r) * D + kc * 8);
            }
            CP_COMMIT();
        }

        // ---- compute 128x128 (this warp: 32x64) ----
        float acc[2][8][4];
        #pragma unroll
        for (int mi = 0; mi < 2; mi++)
            #pragma unroll
            for (int ni = 0; ni < 8; ni++)
                #pragma unroll
                for (int v = 0; v < 4; v++) acc[mi][ni][v] = 0.0f;

        uint32_t bbase = sb + OFF_B + (c & 1) * 32768;
        uint32_t abase = sb + OFF_A;
        #pragma unroll
        for (int kk = 0; kk < 8; kk++) {
            uint32_t af[2][4];
            int kbA = kk * 32 + ((lane >> 4) << 4);
            int hA = kbA >> 7, wA = kbA & 127;
            #pragma unroll
            for (int mi = 0; mi < 2; mi++) {
                int row = wr * 32 + mi * 16 + (lane & 15);
                uint32_t ad = abase + hA * 16384 + row * 128
                            + (wA ^ ((row & 7) << 4));
                LDSM4(af[mi], ad);
            }
            uint32_t bf[4][4];
            int kbB = kk * 32 + (((lane >> 3) & 1) << 4);
            int hB = kbB >> 7, wB = kbB & 127;
            #pragma unroll
            for (int g = 0; g < 4; g++) {
                int col = wc * 64 + g * 16 + (lane & 7) + (((lane >> 4) & 1) << 3);
                uint32_t bd = bbase + hB * 16384 + col * 128
                            + (wB ^ ((col & 7) << 4));
                LDSM4(bf[g], bd);
            }
            #pragma unroll
            for (int mi = 0; mi < 2; mi++)
                #pragma unroll
                for (int g = 0; g < 4; g++) {
                    MMA(acc[mi][2 * g],     af[mi], bf[g][0], bf[g][1]);
                    MMA(acc[mi][2 * g + 1], af[mi], bf[g][2], bf[g][3]);
                }
        }

        const float4* stage4 = (const float4*)(smraw + OFF_STAGE + (c & 1) * 1024);

        if (d == 0) {
            // ---- diagonal: row stats only, self-exclusion ----
            #pragma unroll
            for (int ni = 0; ni < 8; ni++) {
                float4 sv = stage4[(colbase >> 1) + ni * 4];
                #pragma unroll
                for (int mi = 0; mi < 2; mi++)
                    #pragma unroll
                    for (int v = 0; v < 4; v++) {
                        int slot = mi * 2 + (v >> 1);
                        int b    = v & 1;
                        float sqj = b ? sv.z : sv.x;
                        int   tgj = __float_as_int(b ? sv.w : sv.y);
                        int cl = colbase + ni * 8 + b;
                        float d2 = fmaxf(fmaf(-2.0f, acc[mi][ni][v],
                                              sqi[slot] + sqj), 1e-12f);
                        if (tgj == tgi[slot]) {
                            if (j0 + cl != rowg[slot]) {
                                ps[slot] += d2;
                                pmax[slot] = fmaxf(pmax[slot], d2);
                            }
                        } else {
                            ns[slot] += d2;
                            nmin[slot] = fminf(nmin[slot], d2);
                        }
                    }
            }
        } else {
            // ---- off-diagonal: row stats + column stats ----
            #pragma unroll
            for (int ni = 0; ni < 8; ni++) {
                float4 sv = stage4[(colbase >> 1) + ni * 4];
                float cps0 = 0.0f, cpm0 = 0.0f, cns0 = 0.0f, cnm0 = FINF;
                float cps1 = 0.0f, cpm1 = 0.0f, cns1 = 0.0f, cnm1 = FINF;
                #pragma unroll
                for (int mi = 0; mi < 2; mi++)
                    #pragma unroll
                    for (int hv = 0; hv < 2; hv++) {
                        int slot = mi * 2 + hv;
                        float d20 = fmaxf(fmaf(-2.0f, acc[mi][ni][hv * 2],
                                               sqi[slot] + sv.x), 1e-12f);
                        if (__float_as_int(sv.y) == tgi[slot]) {
                            ps[slot] += d20; pmax[slot] = fmaxf(pmax[slot], d20);
                            cps0 += d20; cpm0 = fmaxf(cpm0, d20);
                        } else {
                            ns[slot] += d20; nmin[slot] = fminf(nmin[slot], d20);
                            cns0 += d20; cnm0 = fminf(cnm0, d20);
                        }
                        float d21 = fmaxf(fmaf(-2.0f, acc[mi][ni][hv * 2 + 1],
                                               sqi[slot] + sv.z), 1e-12f);
                        if (__float_as_int(sv.w) == tgi[slot]) {
                            ps[slot] += d21; pmax[slot] = fmaxf(pmax[slot], d21);
                            cps1 += d21; cpm1 = fmaxf(cpm1, d21);
                        } else {
                            ns[slot] += d21; nmin[slot] = fminf(nmin[slot], d21);
                            cns1 += d21; cnm1 = fminf(cnm1, d21);
                        }
                    }
                // reduce col stats over the 8 row-lanes (xor 4,8,16)
                #pragma unroll
                for (int o = 4; o <= 16; o <<= 1) {
                    cps0 += __shfl_xor_sync(0xffffffffu, cps0, o);
                    cpm0 = fmaxf(cpm0, __shfl_xor_sync(0xffffffffu, cpm0, o));
                    cns0 += __shfl_xor_sync(0xffffffffu, cns0, o);
                    cnm0 = fminf(cnm0, __shfl_xor_sync(0xffffffffu, cnm0, o));
                    cps1 += __shfl_xor_sync(0xffffffffu, cps1, o);
                    cpm1 = fmaxf(cpm1, __shfl_xor_sync(0xffffffffu, cpm1, o));
                    cns1 += __shfl_xor_sync(0xffffffffu, cns1, o);
                    cnm1 = fminf(cnm1, __shfl_xor_sync(0xffffffffu, cnm1, o));
                }
                int stat = (lane >> 2) & 3;
                int b    = lane >> 4;
                float v0 = b ? ((stat & 2) ? ((stat & 1) ? cnm1 : cns1)
                                           : ((stat & 1) ? cpm1 : cps1))
                             : ((stat & 2) ? ((stat & 1) ? cnm0 : cns0)
                                           : ((stat & 1) ? cpm0 : cps0));
                int col = colbase + ni * 8 + b;
                scol[wr * 512 + col * 4 + stat] = v0;
            }
            __syncthreads();
            if (tid < 128) {
                const float4* sc = (const float4*)scol;
                float4 s0 = sc[tid], s1 = sc[128 + tid];
                float4 s2 = sc[256 + tid], s3 = sc[384 + tid];
                float aps = s0.x + s1.x + s2.x + s3.x;
                float apm = fmaxf(fmaxf(s0.y, s1.y), fmaxf(s2.y, s3.y));
                float ans = s0.z + s1.z + s2.z + s3.z;
                float anm = fminf(fminf(s0.w, s1.w), fminf(s2.w, s3.w));
                int row = j0 + tid;
                atomicAdd(&g_ps[row], aps);
                atomicMax(&g_pm[row], __float_as_int(apm));
                atomicAdd(&g_ns[row], ans);
                atomicMin(&g_nm[row], __float_as_int(anm));
            }
        }
    }

    // ---- merge this block's register row stats ----
    #pragma unroll
    for (int q = 0; q < 4; q++) {
        float a = ps[q], b = pmax[q], cn = ns[q], dd = nmin[q];
        #pragma unroll
        for (int o = 1; o <= 2; o <<= 1) {
            a  += __shfl_xor_sync(0xffffffffu, a, o);
            b   = fmaxf(b, __shfl_xor_sync(0xffffffffu, b, o));
            cn += __shfl_xor_sync(0xffffffffu, cn, o);
            dd  = fminf(dd, __shfl_xor_sync(0xffffffffu, dd, o));
        }
        if ((lane & 3) == 0) {
            int row = rowg[q];
            atomicAdd(&g_ps[row], a);
            atomicMax(&g_pm[row], __float_as_int(b));
            atomicAdd(&g_ns[row], cn);
            atomicMin(&g_nm[row], __float_as_int(dd));
        }
    }
}

// ---------------------------------------------------------------------------
// Hinge per row + fused final sum (last-block-done pattern).
// ---------------------------------------------------------------------------
__global__ void hinge_kernel(float* __restrict__ out) {
    __shared__ float smr[256];
    __shared__ int last;
    int row = blockIdx.x * 256 + threadIdx.x;
    float psum = g_ps[row];
    float pmax = __int_as_float(g_pm[row]);
    float nsum = g_ns[row];
    float nmin = __int_as_float(g_nm[row]);
    int tg = __float_as_int(g_sqtg[row].y);
    int cc = g_cc[tg];
    float sp = psum / (float)(cc - 1);
    float ap = pmax / sp + 0.5f * logf(sp);
    float sn = nsum / (float)(N - cc);
    float an = nmin / sn + 0.5f * logf(sn);
    float h = fmaxf(ap - an + MARGIN, 0.0f);

    smr[threadIdx.x] = h;
    __syncthreads();
    for (int o = 128; o > 0; o >>= 1) {
        if (threadIdx.x < o) smr[threadIdx.x] += smr[threadIdx.x + o];
        __syncthreads();
    }
    if (threadIdx.x == 0) {
        g_bsum[blockIdx.x] = smr[0];
        __threadfence();
        int t = atomicAdd(&g_done, 1);
        last = (t == 31);
    }
    __syncthreads();
    if (last && threadIdx.x < 32) {
        __threadfence();
        float v = ((volatile float*)g_bsum)[threadIdx.x];
        #pragma unroll
        for (int o = 16; o > 0; o >>= 1) v += __shfl_xor_sync(0xffffffffu, v, o);
        if (threadIdx.x == 0) {
            out[0] = v / (float)N;
            g_done = 0;
        }
    }
}

extern "C" void kernel_launch(void* const* d_in, const int* in_sizes, int n_in,
                              void* d_out, int out_size) {
    (void)in_sizes; (void)n_in; (void)out_size;
    const float* x   = (const float*)d_in[0];
    const void*  tgt = d_in[1];

    detect_kernel<<<1, 256>>>((const unsigned int*)tgt);
    prep_kernel<<<128, 256>>>(x, tgt);

    cudaFuncSetAttribute(main_kernel, cudaFuncAttributeMaxDynamicSharedMemorySize, SMEM_REQ);
    main_kernel<<<128, 256, SMEM_REQ>>>();

    hinge_kernel<<<32, 256>>>((float*)d_out);
}

// round 17
// speedup vs baseline: 3.3574x; 1.2557x over previous
#include <cuda_runtime.h>
#include <cuda_fp16.h>
#include <cstdint>

#define N 8192
#define D 128
#define MARGIN 0.3f
#define NCLS 256
#define FINF __int_as_float(0x7f800000)

__device__ __half  g_xh[N * D];         // fp16 inputs
__device__ float2  g_sqtg[N];           // (sq_norm fp32, target-as-bits)
__device__ int     g_cc[NCLS];
__device__ int     g_is64;
__device__ float   g_ps[N];             // pos sum
__device__ int     g_pm[N];             // pos max (float bits, >=0)
__device__ float   g_ns[N];             // neg sum
__device__ int     g_nm[N];             // neg min (float bits, >=0)
__device__ float   g_bsum[32];
__device__ int     g_done;              // last-block ticket (self-resetting)

// ---------------- PTX helpers ----------------
__device__ __forceinline__ uint32_t smem_u32(const void* p) {
    uint32_t a;
    asm("{ .reg .u64 t; cvta.to.shared.u64 t, %1; cvt.u32.u64 %0, t; }"
        : "=r"(a) : "l"(p));
    return a;
}
#define CP16(dst, src) \
    asm volatile("cp.async.cg.shared.global [%0], [%1], 16;" \
        :: "r"(dst), "l"(src) : "memory")
#define CP_COMMIT() asm volatile("cp.async.commit_group;" ::: "memory")
#define CP_WAIT(n)  asm volatile("cp.async.wait_group %0;" :: "n"(n) : "memory")

#define LDSM4(r, a) \
    asm volatile("ldmatrix.sync.aligned.m8n8.x4.shared.b16 {%0,%1,%2,%3}, [%4];" \
        : "=r"((r)[0]), "=r"((r)[1]), "=r"((r)[2]), "=r"((r)[3]) : "r"(a))

#define MMA(c, a, b0_, b1_) \
    asm volatile("mma.sync.aligned.m16n8k16.row.col.f32.f16.f16.f32 " \
        "{%0,%1,%2,%3},{%4,%5,%6,%7},{%8,%9},{%0,%1,%2,%3};" \
        : "+f"((c)[0]), "+f"((c)[1]), "+f"((c)[2]), "+f"((c)[3]) \
        : "r"((a)[0]), "r"((a)[1]), "r"((a)[2]), "r"((a)[3]), "r"(b0_), "r"(b1_))

// SMEM: 32KB A, 2x32KB B, 2KB stage, 8KB scol  (=108.5KB -> 2 CTAs/SM)
#define OFF_A     0
#define OFF_B     32768
#define OFF_STAGE 98304
#define OFF_SCOL  100352
#define SMEM_REQ  108544

// ---------------------------------------------------------------------------
__global__ void detect_kernel(const unsigned int* __restrict__ t) {
    __shared__ unsigned int sred[256];
    unsigned int acc = 0;
    for (int i = threadIdx.x; i < N / 2; i += 256) acc |= t[2 * i + 1];
    sred[threadIdx.x] = acc;
    __syncthreads();
    for (int s = 128; s > 0; s >>= 1) {
        if (threadIdx.x < s) sred[threadIdx.x] |= sred[threadIdx.x + s];
        __syncthreads();
    }
    if (threadIdx.x == 0) g_is64 = (sred[0] == 0u) ? 1 : 0;
    if (threadIdx.x < NCLS) g_cc[threadIdx.x] = 0;
}

// fp16 convert + fp32 norms + targets + histogram + stat-array init.
__global__ void prep_kernel(const float* __restrict__ x, const void* __restrict__ tgt) {
    int lane = threadIdx.x & 31;
    int gw   = (blockIdx.x * 8) + (threadIdx.x >> 5);
    const float4* X4 = (const float4*)x;
    uint2* OH = (uint2*)g_xh;
    int is64 = g_is64;

    #pragma unroll
    for (int r = 0; r < 8; r++) {
        int row = gw * 8 + r;
        float4 v = X4[row * 32 + lane];

        __half2 p01 = __floats2half2_rn(v.x, v.y);
        __half2 p23 = __floats2half2_rn(v.z, v.w);
        OH[row * 32 + lane] = make_uint2(*(uint32_t*)&p01, *(uint32_t*)&p23);

        float s = v.x * v.x + v.y * v.y + v.z * v.z + v.w * v.w;
        #pragma unroll
        for (int o = 16; o > 0; o >>= 1) s += __shfl_xor_sync(0xffffffffu, s, o);
        if (lane == 0) {
            int tg;
            if (is64) tg = (int)((const long long*)tgt)[row];
            else      tg = ((const int*)tgt)[row];
            g_sqtg[row] = make_float2(s, __int_as_float(tg));
            atomicAdd(&g_cc[tg], 1);
            g_ps[row] = 0.0f; g_ns[row] = 0.0f;
            g_pm[row] = 0;    g_nm[row] = 0x7f800000;
        }
    }
}

// ---------------------------------------------------------------------------
// Main: symmetric (circulant) fp16 mma.sync distance GEMM + fused stats.
// Grid 256 = 64 row-tiles x 4 parity groups: block (ti, p) handles
// d = p, p+4, ... <= dmax (tj = (ti+d)&63). ~2 CTAs/SM -> one CTA's MMA
// overlaps the other's epilogue/barrier phase.
// ---------------------------------------------------------------------------
__global__ void __launch_bounds__(256, 2) main_kernel() {
    extern __shared__ __align__(1024) char smraw[];
    uint32_t sb = smem_u32(smraw);
    float* scol = (float*)(smraw + OFF_SCOL);          // [wr][col][stat]

    int tid  = threadIdx.x;
    int lane = tid & 31;
    int wid  = tid >> 5;
    int wr   = wid >> 1;
    int wc   = wid & 1;
    int ti   = blockIdx.x >> 2;
    int hk   = blockIdx.x & 3;
    int i0   = ti * 128;
    int dmax = (ti < 32) ? 32 : 31;
    int nc   = ((dmax - hk) >> 2) + 1;                 // 8 or 9 chunks

    // ---- A tile + B chunk 0 (one cp.async group) ----
    {
        int j00 = ((ti + hk) & 63) * 128;
        #pragma unroll
        for (int t = 0; t < 8; t++) {
            int idx = tid + t * 256;
            int r   = idx >> 4;
            int kc  = idx & 15;
            uint32_t so = (kc >> 3) * 16384 + r * 128
                        + (((kc & 7) << 4) ^ ((r & 7) << 4));
            CP16(sb + OFF_A + so, g_xh + (i0 + r) * D + kc * 8);
            CP16(sb + OFF_B + so, g_xh + (j00 + r) * D + kc * 8);
        }
        CP_COMMIT();
    }

    // ---- per-thread stats for 4 fixed rows (registers across all chunks) ----
    float ps[4], pmax[4], ns[4], nmin[4], sqi[4];
    int tgi[4], rowg[4];
    #pragma unroll
    for (int q = 0; q < 4; q++) {
        rowg[q] = i0 + wr * 32 + q * 8 + (lane >> 2);
        float2 st = g_sqtg[rowg[q]];
        sqi[q] = st.x;
        tgi[q] = __float_as_int(st.y);
        ps[q] = 0.0f; ns[q] = 0.0f; pmax[q] = -FINF; nmin[q] = FINF;
    }
    int colbase = wc * 64 + (lane & 3) * 2;

    for (int c = 0; c < nc; c++) {
        int d  = hk + 4 * c;
        int j0 = ((ti + d) & 63) * 128;

        CP_WAIT(0);  // chunk c resident (only group outstanding)
        if (tid < 128)
            *((float2*)(smraw + OFF_STAGE) + (c & 1) * 128 + tid) = g_sqtg[j0 + tid];
        __syncthreads();  // B chunk c + stage visible; epilogue c-1 done

        // prefetch chunk c+1 into the other buffer (overlaps compute c)
        if (c + 1 < nc) {
            int jn = ((ti + d + 4) & 63) * 128;
            uint32_t bdst = sb + OFF_B + ((c + 1) & 1) * 32768;
            #pragma unroll
            for (int t = 0; t < 8; t++) {
                int idx = tid + t * 256;
                int r   = idx >> 4;
                int kc  = idx & 15;
                uint32_t so = (kc >> 3) * 16384 + r * 128
                            + (((kc & 7) << 4) ^ ((r & 7) << 4));
                CP16(bdst + so, g_xh + (jn + r) * D + kc * 8);
            }
            CP_COMMIT();
        }

        // ---- compute 128x128 (this warp: 32x64) ----
        float acc[2][8][4];
        #pragma unroll
        for (int mi = 0; mi < 2; mi++)
            #pragma unroll
            for (int ni = 0; ni < 8; ni++)
                #pragma unroll
                for (int v = 0; v < 4; v++) acc[mi][ni][v] = 0.0f;

        uint32_t bbase = sb + OFF_B + (c & 1) * 32768;
        uint32_t abase = sb + OFF_A;
        #pragma unroll
        for (int kk = 0; kk < 8; kk++) {
            uint32_t af[2][4];
            int kbA = kk * 32 + ((lane >> 4) << 4);
            int hA = kbA >> 7, wA = kbA & 127;
            #pragma unroll
            for (int mi = 0; mi < 2; mi++) {
                int row = wr * 32 + mi * 16 + (lane & 15);
                uint32_t ad = abase + hA * 16384 + row * 128
                            + (wA ^ ((row & 7) << 4));
                LDSM4(af[mi], ad);
            }
            uint32_t bf[4][4];
            int kbB = kk * 32 + (((lane >> 3) & 1) << 4);
            int hB = kbB >> 7, wB = kbB & 127;
            #pragma unroll
            for (int g = 0; g < 4; g++) {
                int col = wc * 64 + g * 16 + (lane & 7) + (((lane >> 4) & 1) << 3);
                uint32_t bd = bbase + hB * 16384 + col * 128
                            + (wB ^ ((col & 7) << 4));
                LDSM4(bf[g], bd);
            }
            #pragma unroll
            for (int mi = 0; mi < 2; mi++)
                #pragma unroll
                for (int g = 0; g < 4; g++) {
                    MMA(acc[mi][2 * g],     af[mi], bf[g][0], bf[g][1]);
                    MMA(acc[mi][2 * g + 1], af[mi], bf[g][2], bf[g][3]);
                }
        }

        const float4* stage4 = (const float4*)(smraw + OFF_STAGE + (c & 1) * 1024);

        if (d == 0) {
            // ---- diagonal: row stats only, self-exclusion ----
            #pragma unroll
            for (int ni = 0; ni < 8; ni++) {
                float4 sv = stage4[(colbase >> 1) + ni * 4];
                #pragma unroll
                for (int mi = 0; mi < 2; mi++)
                    #pragma unroll
                    for (int v = 0; v < 4; v++) {
                        int slot = mi * 2 + (v >> 1);
                        int b    = v & 1;
                        float sqj = b ? sv.z : sv.x;
                        int   tgj = __float_as_int(b ? sv.w : sv.y);
                        int cl = colbase + ni * 8 + b;
                        float d2 = fmaxf(fmaf(-2.0f, acc[mi][ni][v],
                                              sqi[slot] + sqj), 1e-12f);
                        if (tgj == tgi[slot]) {
                            if (j0 + cl != rowg[slot]) {
                                ps[slot] += d2;
                                pmax[slot] = fmaxf(pmax[slot], d2);
                            }
                        } else {
                            ns[slot] += d2;
                            nmin[slot] = fminf(nmin[slot], d2);
                        }
                    }
            }
        } else {
            // ---- off-diagonal: row stats + column stats ----
            #pragma unroll
            for (int ni = 0; ni < 8; ni++) {
                float4 sv = stage4[(colbase >> 1) + ni * 4];
                float cps0 = 0.0f, cpm0 = 0.0f, cns0 = 0.0f, cnm0 = FINF;
                float cps1 = 0.0f, cpm1 = 0.0f, cns1 = 0.0f, cnm1 = FINF;
                #pragma unroll
                for (int mi = 0; mi < 2; mi++)
                    #pragma unroll
                    for (int hv = 0; hv < 2; hv++) {
                        int slot = mi * 2 + hv;
                        float d20 = fmaxf(fmaf(-2.0f, acc[mi][ni][hv * 2],
                                               sqi[slot] + sv.x), 1e-12f);
                        if (__float_as_int(sv.y) == tgi[slot]) {
                            ps[slot] += d20; pmax[slot] = fmaxf(pmax[slot], d20);
                            cps0 += d20; cpm0 = fmaxf(cpm0, d20);
                        } else {
                            ns[slot] += d20; nmin[slot] = fminf(nmin[slot], d20);
                            cns0 += d20; cnm0 = fminf(cnm0, d20);
                        }
                        float d21 = fmaxf(fmaf(-2.0f, acc[mi][ni][hv * 2 + 1],
                                               sqi[slot] + sv.z), 1e-12f);
                        if (__float_as_int(sv.w) == tgi[slot]) {
                            ps[slot] += d21; pmax[slot] = fmaxf(pmax[slot], d21);
                            cps1 += d21; cpm1 = fmaxf(cpm1, d21);
                        } else {
                            ns[slot] += d21; nmin[slot] = fminf(nmin[slot], d21);
                            cns1 += d21; cnm1 = fminf(cnm1, d21);
                        }
                    }
                // reduce col stats over the 8 row-lanes (xor 4,8,16)
                #pragma unroll
                for (int o = 4; o <= 16; o <<= 1) {
                    cps0 += __shfl_xor_sync(0xffffffffu, cps0, o);
                    cpm0 = fmaxf(cpm0, __shfl_xor_sync(0xffffffffu, cpm0, o));
                    cns0 += __shfl_xor_sync(0xffffffffu, cns0, o);
                    cnm0 = fminf(cnm0, __shfl_xor_sync(0xffffffffu, cnm0, o));
                    cps1 += __shfl_xor_sync(0xffffffffu, cps1, o);
                    cpm1 = fmaxf(cpm1, __shfl_xor_sync(0xffffffffu, cpm1, o));
                    cns1 += __shfl_xor_sync(0xffffffffu, cns1, o);
                    cnm1 = fminf(cnm1, __shfl_xor_sync(0xffffffffu, cnm1, o));
                }
                int stat = (lane >> 2) & 3;
                int b    = lane >> 4;
                float v0 = b ? ((stat & 2) ? ((stat & 1) ? cnm1 : cns1)
                                           : ((stat & 1) ? cpm1 : cps1))
                             : ((stat & 2) ? ((stat & 1) ? cnm0 : cns0)
                                           : ((stat & 1) ? cpm0 : cps0));
                int col = colbase + ni * 8 + b;
                scol[wr * 512 + col * 4 + stat] = v0;
            }
            __syncthreads();
            if (tid < 128) {
                const float4* sc = (const float4*)scol;
                float4 s0 = sc[tid], s1 = sc[128 + tid];
                float4 s2 = sc[256 + tid], s3 = sc[384 + tid];
                float aps = s0.x + s1.x + s2.x + s3.x;
                float apm = fmaxf(fmaxf(s0.y, s1.y), fmaxf(s2.y, s3.y));
                float ans = s0.z + s1.z + s2.z + s3.z;
                float anm = fminf(fminf(s0.w, s1.w), fminf(s2.w, s3.w));
                int row = j0 + tid;
                atomicAdd(&g_ps[row], aps);
                atomicMax(&g_pm[row], __float_as_int(apm));
                atomicAdd(&g_ns[row], ans);
                atomicMin(&g_nm[row], __float_as_int(anm));
            }
        }
    }

    // ---- merge this block's register row stats ----
    #pragma unroll
    for (int q = 0; q < 4; q++) {
        float a = ps[q], b = pmax[q], cn = ns[q], dd = nmin[q];
        #pragma unroll
        for (int o = 1; o <= 2; o <<= 1) {
            a  += __shfl_xor_sync(0xffffffffu, a, o);
            b   = fmaxf(b, __shfl_xor_sync(0xffffffffu, b, o));
            cn += __shfl_xor_sync(0xffffffffu, cn, o);
            dd  = fminf(dd, __shfl_xor_sync(0xffffffffu, dd, o));
        }
        if ((lane & 3) == 0) {
            int row = rowg[q];
            atomicAdd(&g_ps[row], a);
            atomicMax(&g_pm[row], __float_as_int(b));
            atomicAdd(&g_ns[row], cn);
            atomicMin(&g_nm[row], __float_as_int(dd));
        }
    }
}

// ---------------------------------------------------------------------------
// Hinge per row + fused final sum (last-block-done pattern).
// ---------------------------------------------------------------------------
__global__ void hinge_kernel(float* __restrict__ out) {
    __shared__ float smr[256];
    __shared__ int last;
    int row = blockIdx.x * 256 + threadIdx.x;
    float psum = g_ps[row];
    float pmax = __int_as_float(g_pm[row]);
    float nsum = g_ns[row];
    float nmin = __int_as_float(g_nm[row]);
    int tg = __float_as_int(g_sqtg[row].y);
    int cc = g_cc[tg];
    float sp = psum / (float)(cc - 1);
    float ap = pmax / sp + 0.5f * logf(sp);
    float sn = nsum / (float)(N - cc);
    float an = nmin / sn + 0.5f * logf(sn);
    float h = fmaxf(ap - an + MARGIN, 0.0f);

    smr[threadIdx.x] = h;
    __syncthreads();
    for (int o = 128; o > 0; o >>= 1) {
        if (threadIdx.x < o) smr[threadIdx.x] += smr[threadIdx.x + o];
        __syncthreads();
    }
    if (threadIdx.x == 0) {
        g_bsum[blockIdx.x] = smr[0];
        __threadfence();
        int t = atomicAdd(&g_done, 1);
        last = (t == 31);
    }
    __syncthreads();
    if (last && threadIdx.x < 32) {
        __threadfence();
        float v = ((volatile float*)g_bsum)[threadIdx.x];
        #pragma unroll
        for (int o = 16; o > 0; o >>= 1) v += __shfl_xor_sync(0xffffffffu, v, o);
        if (threadIdx.x == 0) {
            out[0] = v / (float)N;
            g_done = 0;
        }
    }
}

extern "C" void kernel_launch(void* const* d_in, const int* in_sizes, int n_in,
                              void* d_out, int out_size) {
    (void)in_sizes; (void)n_in; (void)out_size;
    const float* x   = (const float*)d_in[0];
    const void*  tgt = d_in[1];

    detect_kernel<<<1, 256>>>((const unsigned int*)tgt);
    prep_kernel<<<128, 256>>>(x, tgt);

    cudaFuncSetAttribute(main_kernel, cudaFuncAttributeMaxDynamicSharedMemorySize, SMEM_REQ);
    main_kernel<<<256, 256, SMEM_REQ>>>();

    hinge_kernel<<<32, 256>>>((float*)d_out);
}